// round 2
// baseline (speedup 1.0000x reference)
#include <cuda_runtime.h>
#include <cstdint>

#define BATCH  4096
#define NIN    784
#define H1     100
#define H1P    128      // padded hidden for clean float4 tiling
#define H2     10
#define NSTEP  100
#define TBEGIN 20
#define KT     56       // k-chunk per smem stage
#define NCHUNK 14       // 784 / 56
#define NK4    14       // KT / 4

// ---------------- device globals (scratch; no allocation allowed) ----------------
__device__ float g_Wg[NIN * H1P];            // interleaved: [k>>2][h][k&3]
__device__ float g_inner1[BATCH * H1P];
__device__ float g_outer1[2][BATCH * H1P];   // double-buffered over t parity
__device__ float g_inner2[BATCH * H2];
__device__ float g_acc[BATCH * H2];

// ---------------- threefry2x32 (JAX-exact, 20 rounds) ----------------
__device__ __forceinline__ void tf2x32(unsigned k0, unsigned k1,
                                       unsigned x0, unsigned x1,
                                       unsigned &o0, unsigned &o1) {
    unsigned ks2 = k0 ^ k1 ^ 0x1BD11BDAu;
    x0 += k0; x1 += k1;
#define TFR(r) { x0 += x1; x1 = __funnelshift_l(x1, x1, (r)); x1 ^= x0; }
    TFR(13) TFR(15) TFR(26) TFR(6);  x0 += k1;  x1 += ks2 + 1u;
    TFR(17) TFR(29) TFR(16) TFR(24); x0 += ks2; x1 += k0 + 2u;
    TFR(13) TFR(15) TFR(26) TFR(6);  x0 += k0;  x1 += k1 + 3u;
    TFR(17) TFR(29) TFR(16) TFR(24); x0 += k1;  x1 += ks2 + 4u;
    TFR(13) TFR(15) TFR(26) TFR(6);  x0 += ks2; x1 += k0 + 5u;
#undef TFR
    o0 = x0; o1 = x1;
}

// partitionable random_bits (32-bit): bits = o0 ^ o1 of threefry(key, (0, idx))
__device__ __forceinline__ float tf_uniform(unsigned k0, unsigned k1, unsigned idx) {
    unsigned o0, o1;
    tf2x32(k0, k1, 0u, idx, o0, o1);
    unsigned bits = o0 ^ o1;
    return __uint_as_float((bits >> 9) | 0x3f800000u) - 1.0f;
}

// ---------------- init: zero state, build padded/interleaved W1 ----------------
__global__ void init_k(const float* __restrict__ W1) {
    int stride = gridDim.x * blockDim.x;
    int tid = blockIdx.x * blockDim.x + threadIdx.x;
    for (int i = tid; i < BATCH * H1P; i += stride) {
        g_inner1[i] = 0.0f;
        g_outer1[0][i] = 0.0f;
        g_outer1[1][i] = 0.0f;
    }
    for (int i = tid; i < BATCH * H2; i += stride) {
        g_inner2[i] = 0.0f;
        g_acc[i] = 0.0f;
    }
    for (int i = tid; i < NIN * H1P; i += stride) {
        int k = i / H1P;
        int h = i - k * H1P;
        g_Wg[(k >> 2) * (H1P * 4) + h * 4 + (k & 3)] =
            (h < H1) ? W1[k * H1 + h] : 0.0f;
    }
}

// ---------------- per-step kernel: 128 layer1 CTAs + 16 layer2 CTAs ----------------
__global__ void __launch_bounds__(256, 1)
step_k(const float* __restrict__ x,
       const float* __restrict__ b1,
       const float* __restrict__ W2,
       const float* __restrict__ b2,
       unsigned key0, unsigned key1, int t)
{
    __shared__ float sh_xi[32 * KT];          // gated input tile
    __shared__ float sh_ws[KT * H1P];         // W chunk, interleaved [k4][h][4]
    __shared__ float sh_w2[H1 * H2];
    __shared__ float sh_b2[H2];

    const int tid = threadIdx.x;

    if (blockIdx.x < 128) {
        // ================= LAYER 1 =================
        const int hq = tid & 31;              // h lane: h = hq + 32*jj
        const int rq = tid >> 5;              // row group: rows rq*4 .. rq*4+3
        const int r0 = blockIdx.x * 32;       // 32 batch rows per CTA
        float* __restrict__ outw = g_outer1[t & 1];

        float acc[4][4];
        #pragma unroll
        for (int a = 0; a < 4; ++a)
            #pragma unroll
            for (int b = 0; b < 4; ++b) acc[a][b] = 0.0f;

        for (int c = 0; c < NCHUNK; ++c) {
            __syncthreads();  // previous chunk fully consumed

            // stage W chunk (contiguous copy, 7168 floats)
            {
                const float4* wsrc = (const float4*)(g_Wg + c * (KT * H1P));
                float4* wdst = (float4*)sh_ws;
                #pragma unroll
                for (int i = 0; i < 7; ++i)
                    wdst[tid + i * 256] = wsrc[tid + i * 256];
            }
            // produce gated inputs: 32 rows x 56 k = 1792 uniforms
            {
                const int kc = c * KT;
                #pragma unroll
                for (int i = 0; i < 7; ++i) {
                    int f = tid + i * 256;
                    int rl = f / KT;
                    int kl = f - rl * KT;
                    unsigned j = (unsigned)((r0 + rl) * NIN + kc + kl);
                    float u = tf_uniform(key0, key1, j);
                    sh_xi[rl * KT + kl] = u * x[j];
                }
            }
            __syncthreads();

            // GEMM: 32 rows x 128 h over this k-chunk
            #pragma unroll
            for (int k4 = 0; k4 < NK4; ++k4) {
                float4 xv[4];
                #pragma unroll
                for (int rr = 0; rr < 4; ++rr)
                    xv[rr] = *(const float4*)&sh_xi[(rq * 4 + rr) * KT + k4 * 4];
                #pragma unroll
                for (int jj = 0; jj < 4; ++jj) {
                    float4 wv = *(const float4*)&sh_ws[k4 * (H1P * 4) + (hq + 32 * jj) * 4];
                    #pragma unroll
                    for (int rr = 0; rr < 4; ++rr) {
                        float a = acc[rr][jj];
                        a = fmaf(xv[rr].x, wv.x, a);
                        a = fmaf(xv[rr].y, wv.y, a);
                        a = fmaf(xv[rr].z, wv.z, a);
                        a = fmaf(xv[rr].w, wv.w, a);
                        acc[rr][jj] = a;
                    }
                }
            }
        }

        // LIF update for layer 1
        #pragma unroll
        for (int rr = 0; rr < 4; ++rr) {
            int r = r0 + rq * 4 + rr;
            #pragma unroll
            for (int jj = 0; jj < 4; ++jj) {
                int h = hq + 32 * jj;
                float exc = acc[rr][jj] + ((h < H1) ? b1[h] : 0.0f);
                float pi  = g_inner1[r * H1P + h];
                float ni  = fmaf(pi, 0.9f, exc);
                float d   = ni - 1.0f;
                float ou  = d > 0.0f ? d : 0.0f;
                outw[r * H1P + h] = ou;
                if (ou > 0.0f) ni = ni - 1.5f * ni;   // penalty reset (Sterbenz-exact)
                g_inner1[r * H1P + h] = ni;
            }
        }
    } else {
        // ================= LAYER 2 =================
        for (int i = tid; i < H1 * H2; i += 256) sh_w2[i] = W2[i];
        if (tid < H2) sh_b2[tid] = b2[tid];
        __syncthreads();

        int r = (blockIdx.x - 128) * 256 + tid;     // one row per thread, 4096 total
        const float* __restrict__ po = g_outer1[(t & 1) ^ 1] + r * H1P;  // delayed outer1

        float s[H2];
        #pragma unroll
        for (int h2 = 0; h2 < H2; ++h2) s[h2] = sh_b2[h2];

        for (int k = 0; k < H1; k += 4) {
            float4 p = *(const float4*)&po[k];
            #pragma unroll
            for (int h2 = 0; h2 < H2; ++h2) {
                float a = s[h2];
                a = fmaf(p.x, sh_w2[(k + 0) * H2 + h2], a);
                a = fmaf(p.y, sh_w2[(k + 1) * H2 + h2], a);
                a = fmaf(p.z, sh_w2[(k + 2) * H2 + h2], a);
                a = fmaf(p.w, sh_w2[(k + 3) * H2 + h2], a);
                s[h2] = a;
            }
        }

        #pragma unroll
        for (int h2 = 0; h2 < H2; ++h2) {
            float pi = g_inner2[r * H2 + h2];
            if (t >= TBEGIN) g_acc[r * H2 + h2] += pi;   // collect DELAYED state
            float ni = fmaf(pi, 0.9f, s[h2]);
            float d  = ni - 1.0f;
            if (d > 0.0f) ni = ni - 1.5f * ni;
            g_inner2[r * H2 + h2] = ni;
        }
    }
}

// ---------------- finalize: log_softmax over accumulated states ----------------
__global__ void final_k(float* __restrict__ out) {
    int r = blockIdx.x * blockDim.x + threadIdx.x;
    if (r >= BATCH) return;
    float v[H2];
    float m = -3.402823466e38f;
    #pragma unroll
    for (int c = 0; c < H2; ++c) {
        v[c] = g_acc[r * H2 + c];
        m = fmaxf(m, v[c]);
    }
    float sum = 0.0f;
    #pragma unroll
    for (int c = 0; c < H2; ++c) sum += expf(v[c] - m);
    float l = logf(sum);
    #pragma unroll
    for (int c = 0; c < H2; ++c) out[r * H2 + c] = v[c] - m - l;
}

// ---------------- host-side threefry (for per-step keys; pure & deterministic) ----
static inline unsigned h_rotl(unsigned v, int r) { return (v << r) | (v >> (32 - r)); }
static void host_tf2x32(unsigned k0, unsigned k1, unsigned x0, unsigned x1,
                        unsigned* o0, unsigned* o1) {
    unsigned ks2 = k0 ^ k1 ^ 0x1BD11BDAu;
    x0 += k0; x1 += k1;
#define HTFR(r) { x0 += x1; x1 = h_rotl(x1, (r)); x1 ^= x0; }
    HTFR(13) HTFR(15) HTFR(26) HTFR(6);  x0 += k1;  x1 += ks2 + 1u;
    HTFR(17) HTFR(29) HTFR(16) HTFR(24); x0 += ks2; x1 += k0 + 2u;
    HTFR(13) HTFR(15) HTFR(26) HTFR(6);  x0 += k0;  x1 += k1 + 3u;
    HTFR(17) HTFR(29) HTFR(16) HTFR(24); x0 += k1;  x1 += ks2 + 4u;
    HTFR(13) HTFR(15) HTFR(26) HTFR(6);  x0 += ks2; x1 += k0 + 5u;
#undef HTFR
    *o0 = x0; *o1 = x1;
}

extern "C" void kernel_launch(void* const* d_in, const int* in_sizes, int n_in,
                              void* d_out, int out_size) {
    const float* x  = (const float*)d_in[0];
    const float* W1 = (const float*)d_in[1];
    const float* b1 = (const float*)d_in[2];
    const float* W2 = (const float*)d_in[3];
    const float* b2 = (const float*)d_in[4];
    float* out = (float*)d_out;

    init_k<<<1024, 256>>>(W1);

    for (int t = 0; t < NSTEP; ++t) {
        // fold-like split (threefry_partitionable): key_t = threefry((0,42), (0,t))
        unsigned k0, k1;
        host_tf2x32(0u, 42u, 0u, (unsigned)t, &k0, &k1);
        step_k<<<144, 256>>>(x, b1, W2, b2, k0, k1, t);
    }

    final_k<<<16, 256>>>(out);
    (void)in_sizes; (void)n_in; (void)out_size;
}

// round 3
// speedup vs baseline: 1.0479x; 1.0479x over previous
#include <cuda_runtime.h>
#include <cstdint>

#define BATCH  4096
#define NIN    784
#define H1     100
#define H1P    128      // padded hidden
#define H2     10
#define NSTEP  100
#define TBEGIN 20
#define KT     56       // k-chunk per smem stage
#define NCHUNK 14       // 784 / 56
#define NK4    14       // KT / 4
#define RT     16       // batch rows per layer-1 CTA
#define L1CTAS 256      // 4096 / 16
#define XI_ELE (RT * KT)   // 896 gated inputs per chunk

// ---------------- device globals (scratch; no allocation allowed) ----------------
__device__ float g_Wg[NIN * H1P];            // interleaved: [k>>2][h][k&3]
__device__ float g_inner1[BATCH * H1P];
__device__ float g_outer1[2][BATCH * H1P];   // double-buffered over t parity
__device__ float g_inner2[BATCH * H2];
__device__ float g_acc[BATCH * H2];

// ---------------- packed fp32x2 FMA (sm_103a dual fp32 pipe) ----------------
__device__ __forceinline__ void ffma2(unsigned long long &a,
                                      unsigned long long xv,
                                      unsigned long long wv) {
    asm("fma.rn.f32x2 %0, %1, %2, %0;" : "+l"(a) : "l"(xv), "l"(wv));
}
__device__ __forceinline__ float fold2(unsigned long long a) {
    float lo, hi;
    asm("mov.b64 {%0,%1}, %2;" : "=f"(lo), "=f"(hi) : "l"(a));
    return lo + hi;
}

// ---------------- threefry2x32 (JAX-exact, 20 rounds) ----------------
__device__ __forceinline__ void tf2x32(unsigned k0, unsigned k1,
                                       unsigned x0, unsigned x1,
                                       unsigned &o0, unsigned &o1) {
    unsigned ks2 = k0 ^ k1 ^ 0x1BD11BDAu;
    x0 += k0; x1 += k1;
#define TFR(r) { x0 += x1; x1 = __funnelshift_l(x1, x1, (r)); x1 ^= x0; }
    TFR(13) TFR(15) TFR(26) TFR(6);  x0 += k1;  x1 += ks2 + 1u;
    TFR(17) TFR(29) TFR(16) TFR(24); x0 += ks2; x1 += k0 + 2u;
    TFR(13) TFR(15) TFR(26) TFR(6);  x0 += k0;  x1 += k1 + 3u;
    TFR(17) TFR(29) TFR(16) TFR(24); x0 += k1;  x1 += ks2 + 4u;
    TFR(13) TFR(15) TFR(26) TFR(6);  x0 += ks2; x1 += k0 + 5u;
#undef TFR
    o0 = x0; o1 = x1;
}

// partitionable random_bits: bits = o0 ^ o1 of threefry(key, (0, idx))
__device__ __forceinline__ float tf_uniform(unsigned k0, unsigned k1, unsigned idx) {
    unsigned o0, o1;
    tf2x32(k0, k1, 0u, idx, o0, o1);
    unsigned bits = o0 ^ o1;
    return __uint_as_float((bits >> 9) | 0x3f800000u) - 1.0f;
}

// ---------------- init: zero state, build padded/interleaved W1 ----------------
__global__ void init_k(const float* __restrict__ W1) {
    int stride = gridDim.x * blockDim.x;
    int tid = blockIdx.x * blockDim.x + threadIdx.x;
    for (int i = tid; i < BATCH * H1P; i += stride) {
        g_inner1[i] = 0.0f;
        g_outer1[0][i] = 0.0f;
        g_outer1[1][i] = 0.0f;
    }
    for (int i = tid; i < BATCH * H2; i += stride) {
        g_inner2[i] = 0.0f;
        g_acc[i] = 0.0f;
    }
    for (int i = tid; i < NIN * H1P; i += stride) {
        int k = i / H1P;
        int h = i - k * H1P;
        g_Wg[(k >> 2) * (H1P * 4) + h * 4 + (k & 3)] =
            (h < H1) ? W1[k * H1 + h] : 0.0f;
    }
}

// ---------------- per-step kernel: 256 layer1 CTAs + 16 layer2 CTAs ----------------
__global__ void __launch_bounds__(256, 2)
step_k(const float* __restrict__ x,
       const float* __restrict__ b1,
       const float* __restrict__ W2,
       const float* __restrict__ b2,
       unsigned key0, unsigned key1, int t)
{
    __shared__ float sh_xi[XI_ELE];           // gated input tile [16 rows][56 k]
    __shared__ float sh_ws[KT * H1P];         // W chunk, interleaved [k4][h][4]
    __shared__ float sh_w2[H1 * H2];
    __shared__ float sh_b2[H2];

    const int tid = threadIdx.x;

    if (blockIdx.x < L1CTAS) {
        // ================= LAYER 1 =================
        const int hq   = tid & 31;
        const int warp = tid >> 5;
        const int rq   = warp & 3;            // row group: rows rq*4 .. rq*4+3
        const int jh   = warp >> 2;           // h half: jj in {2jh, 2jh+1}
        const int r0   = blockIdx.x * RT;
        float* __restrict__ outw = g_outer1[t & 1];

        // accumulators: [4 rows][2 h-tiles], each a packed (even-k, odd-k) pair
        unsigned long long acc2[4][2];
        #pragma unroll
        for (int a = 0; a < 4; ++a) { acc2[a][0] = 0ull; acc2[a][1] = 0ull; }

        // prefetch registers
        float4 wreg[7];
        float  xreg[4];

        // prologue: load chunk 0
        {
            const float4* wsrc = (const float4*)g_Wg;
            #pragma unroll
            for (int i = 0; i < 7; ++i) wreg[i] = wsrc[tid + i * 256];
            #pragma unroll
            for (int i = 0; i < 4; ++i) {
                int f = tid + i * 256;
                xreg[i] = (f < XI_ELE) ? x[(r0 + f / KT) * NIN + (f % KT)] : 0.0f;
            }
        }

        for (int c = 0; c < NCHUNK; ++c) {
            // ---- stage chunk c from regs into smem ----
            {
                float4* wdst = (float4*)sh_ws;
                #pragma unroll
                for (int i = 0; i < 7; ++i) wdst[tid + i * 256] = wreg[i];
                const int kc = c * KT;
                #pragma unroll
                for (int i = 0; i < 4; ++i) {
                    int f = tid + i * 256;
                    if (f < XI_ELE) {
                        unsigned j = (unsigned)((r0 + f / KT) * NIN + kc + (f % KT));
                        sh_xi[f] = tf_uniform(key0, key1, j) * xreg[i];
                    }
                }
            }
            // ---- prefetch chunk c+1 (latency hidden by GEMM below) ----
            if (c + 1 < NCHUNK) {
                const float4* wsrc = (const float4*)(g_Wg + (c + 1) * (KT * H1P));
                #pragma unroll
                for (int i = 0; i < 7; ++i) wreg[i] = wsrc[tid + i * 256];
                const int kn = (c + 1) * KT;
                #pragma unroll
                for (int i = 0; i < 4; ++i) {
                    int f = tid + i * 256;
                    xreg[i] = (f < XI_ELE) ? x[(r0 + f / KT) * NIN + kn + (f % KT)] : 0.0f;
                }
            }
            __syncthreads();

            // ---- GEMM over this chunk: 16 rows x 128 h ----
            #pragma unroll
            for (int k4 = 0; k4 < NK4; ++k4) {
                ulonglong2 wv0 = *(const ulonglong2*)&sh_ws[k4 * (H1P * 4) + (hq + 32 * (2 * jh + 0)) * 4];
                ulonglong2 wv1 = *(const ulonglong2*)&sh_ws[k4 * (H1P * 4) + (hq + 32 * (2 * jh + 1)) * 4];
                #pragma unroll
                for (int rr = 0; rr < 4; ++rr) {
                    ulonglong2 xv = *(const ulonglong2*)&sh_xi[(rq * 4 + rr) * KT + k4 * 4];
                    ffma2(acc2[rr][0], xv.x, wv0.x);
                    ffma2(acc2[rr][0], xv.y, wv0.y);
                    ffma2(acc2[rr][1], xv.x, wv1.x);
                    ffma2(acc2[rr][1], xv.y, wv1.y);
                }
            }
            __syncthreads();   // GEMM reads done before next stage overwrites
        }

        // ---- LIF update for layer 1 ----
        #pragma unroll
        for (int rr = 0; rr < 4; ++rr) {
            int r = r0 + rq * 4 + rr;
            #pragma unroll
            for (int jp = 0; jp < 2; ++jp) {
                int h = hq + 32 * (2 * jh + jp);
                float exc = fold2(acc2[rr][jp]) + ((h < H1) ? b1[h] : 0.0f);
                float pi  = g_inner1[r * H1P + h];
                float ni  = fmaf(pi, 0.9f, exc);
                float d   = ni - 1.0f;
                float ou  = d > 0.0f ? d : 0.0f;
                outw[r * H1P + h] = ou;
                if (ou > 0.0f) ni = ni - 1.5f * ni;   // penalty reset
                g_inner1[r * H1P + h] = ni;
            }
        }
    } else {
        // ================= LAYER 2 =================
        for (int i = tid; i < H1 * H2; i += 256) sh_w2[i] = W2[i];
        if (tid < H2) sh_b2[tid] = b2[tid];
        __syncthreads();

        int r = (blockIdx.x - L1CTAS) * 256 + tid;  // one row per thread
        const float* __restrict__ po = g_outer1[(t & 1) ^ 1] + r * H1P;  // delayed outer1

        float s[H2];
        #pragma unroll
        for (int h2 = 0; h2 < H2; ++h2) s[h2] = sh_b2[h2];

        for (int k = 0; k < H1; k += 4) {
            float4 p = *(const float4*)&po[k];
            #pragma unroll
            for (int h2 = 0; h2 < H2; ++h2) {
                float a = s[h2];
                a = fmaf(p.x, sh_w2[(k + 0) * H2 + h2], a);
                a = fmaf(p.y, sh_w2[(k + 1) * H2 + h2], a);
                a = fmaf(p.z, sh_w2[(k + 2) * H2 + h2], a);
                a = fmaf(p.w, sh_w2[(k + 3) * H2 + h2], a);
                s[h2] = a;
            }
        }

        #pragma unroll
        for (int h2 = 0; h2 < H2; ++h2) {
            float pi = g_inner2[r * H2 + h2];
            if (t >= TBEGIN) g_acc[r * H2 + h2] += pi;   // collect DELAYED state
            float ni = fmaf(pi, 0.9f, s[h2]);
            float d  = ni - 1.0f;
            if (d > 0.0f) ni = ni - 1.5f * ni;
            g_inner2[r * H2 + h2] = ni;
        }
    }
}

// ---------------- finalize: log_softmax over accumulated states ----------------
__global__ void final_k(float* __restrict__ out) {
    int r = blockIdx.x * blockDim.x + threadIdx.x;
    if (r >= BATCH) return;
    float v[H2];
    float m = -3.402823466e38f;
    #pragma unroll
    for (int c = 0; c < H2; ++c) {
        v[c] = g_acc[r * H2 + c];
        m = fmaxf(m, v[c]);
    }
    float sum = 0.0f;
    #pragma unroll
    for (int c = 0; c < H2; ++c) sum += expf(v[c] - m);
    float l = logf(sum);
    #pragma unroll
    for (int c = 0; c < H2; ++c) out[r * H2 + c] = v[c] - m - l;
}

// ---------------- host-side threefry (per-step keys) ----------------
static inline unsigned h_rotl(unsigned v, int r) { return (v << r) | (v >> (32 - r)); }
static void host_tf2x32(unsigned k0, unsigned k1, unsigned x0, unsigned x1,
                        unsigned* o0, unsigned* o1) {
    unsigned ks2 = k0 ^ k1 ^ 0x1BD11BDAu;
    x0 += k0; x1 += k1;
#define HTFR(r) { x0 += x1; x1 = h_rotl(x1, (r)); x1 ^= x0; }
    HTFR(13) HTFR(15) HTFR(26) HTFR(6);  x0 += k1;  x1 += ks2 + 1u;
    HTFR(17) HTFR(29) HTFR(16) HTFR(24); x0 += ks2; x1 += k0 + 2u;
    HTFR(13) HTFR(15) HTFR(26) HTFR(6);  x0 += k0;  x1 += k1 + 3u;
    HTFR(17) HTFR(29) HTFR(16) HTFR(24); x0 += k1;  x1 += ks2 + 4u;
    HTFR(13) HTFR(15) HTFR(26) HTFR(6);  x0 += ks2; x1 += k0 + 5u;
#undef HTFR
    *o0 = x0; *o1 = x1;
}

extern "C" void kernel_launch(void* const* d_in, const int* in_sizes, int n_in,
                              void* d_out, int out_size) {
    const float* x  = (const float*)d_in[0];
    const float* W1 = (const float*)d_in[1];
    const float* b1 = (const float*)d_in[2];
    const float* W2 = (const float*)d_in[3];
    const float* b2 = (const float*)d_in[4];
    float* out = (float*)d_out;

    init_k<<<1024, 256>>>(W1);

    for (int t = 0; t < NSTEP; ++t) {
        unsigned k0, k1;
        host_tf2x32(0u, 42u, 0u, (unsigned)t, &k0, &k1);
        step_k<<<L1CTAS + 16, 256>>>(x, b1, W2, b2, k0, k1, t);
    }

    final_k<<<16, 256>>>(out);
    (void)in_sizes; (void)n_in; (void)out_size;
}